// round 13
// baseline (speedup 1.0000x reference)
#include <cuda_runtime.h>
#include <cstdint>

#define L_SEQ   2048
#define D_DIM   64
#define TILE    128
#define R_BAND  128
#define NTILE   16
#define ZDIM    32               // B*H
#define KT_S    132              // Kt row stride in floats (128 + pad)

#define N_BAND_PER_Z 46
#define N_BAND   (N_BAND_PER_Z * ZDIM)   // 1472
#define N_FILL_CTAS 1024                 // 64 units each; 65536 units total

typedef unsigned long long ull;

__device__ __forceinline__ void fma2(ull& d, ull a, ull b)
{
    asm("fma.rn.f32x2 %0, %1, %2, %0;" : "+l"(d) : "l"(a), "l"(b));
}

__device__ __forceinline__ ull dup2(float v)
{
    ull r;
    asm("mov.b64 %0, {%1, %1};" : "=l"(r) : "f"(v));
    return r;
}

__device__ __forceinline__ float2 unpack2(ull v)
{
    float2 f;
    asm("mov.b64 {%0, %1}, %2;" : "=f"(f.x), "=f"(f.y) : "l"(v));
    return f;
}

__device__ __forceinline__ uint32_t smem_u32(const void* p)
{
    uint32_t a;
    asm("{ .reg .u64 t; cvta.to.shared.u64 t, %1; cvt.u32.u64 %0, t; }"
        : "=r"(a) : "l"(p));
    return a;
}

__device__ __forceinline__ void bulk_store(void* gdst, uint32_t ssrc, uint32_t bytes)
{
    asm volatile("cp.async.bulk.global.shared::cta.bulk_group [%0], [%1], %2;"
                 :: "l"(gdst), "r"(ssrc), "r"(bytes) : "memory");
}

// ======================= fill kernel (co-resident) ========================
// 1024 CTAs x 128 threads, 8 KiB static smem, ~16 regs.
// Each of threads 0..63 issues the merged zero-span of one row-unit.
__global__ __launch_bounds__(128)
void zero_fill_kernel(float* __restrict__ out)
{
    __shared__ float4 zb[512];   // 8 KiB of zeros
    const int tid = threadIdx.x;

    #pragma unroll
    for (int i = tid; i < 512; i += 128)
        zb[i] = make_float4(0.f, 0.f, 0.f, 0.f);
    __syncthreads();

    if (tid < 64) {
        asm volatile("fence.proxy.async.shared::cta;" ::: "memory");
        const uint32_t zbuf = smem_u32(zb);

        const int ug = blockIdx.x * 64 + tid;     // 0..65535 global row-unit
        const int z  = ug >> 11;                  // 0..31
        const int u  = ug & 2047;                 // unit within z
        const int s  = u >> 7;                    // stripe 0..15
        const int r  = u & 127;                   // row-unit 0..127

        const int lo = (s > 0)  ? s - 1 : 0;
        const int hi = (s < 15) ? s + 1 : 15;
        const uint32_t suf_off = (uint32_t)(hi + 1) * 512u;

        char* sbase = (char*)out + (size_t)z * L_SEQ * L_SEQ * 4
                                 + (size_t)s * TILE * 8192;

        if (r < 127) {
            // merged span: suffix of row r + prefix of row r+1 (contiguous)
            const uint32_t chunk = (uint32_t)((15 - hi) + lo) * 512u;
            if (chunk)
                bulk_store(sbase + (size_t)r * 8192 + suf_off, zbuf, chunk);
        } else {
            if (hi < 15)
                bulk_store(sbase + (size_t)127 * 8192 + suf_off,
                           zbuf, (uint32_t)(15 - hi) * 512u);
            if (lo > 0)
                bulk_store(sbase, zbuf, (uint32_t)lo * 512u);
        }
        asm volatile("cp.async.bulk.commit_group;" ::: "memory");
        asm volatile("cp.async.bulk.wait_group 0;" ::: "memory");
    }
}

// ======================= band kernel (R10 band path) ======================
extern __shared__ float4 smem4[];

__global__ __launch_bounds__(256, 2)
void band_scores_kernel(const float* __restrict__ Q,
                        const float* __restrict__ K,
                        float* __restrict__ out)
{
    const int bid = blockIdx.x;
    const int tid = threadIdx.x;

    const int z = bid / N_BAND_PER_Z;
    const int n = bid - z * N_BAND_PER_Z;      // 0..45
    const int ti = (n + 1) / 3;
    const int tj = ti - 1 + ((n + 1) % 3);

    float* outTile = out + ((size_t)z * L_SEQ + (size_t)ti * TILE) * L_SEQ
                         + (size_t)tj * TILE;

    float4* Qs4 = smem4;                              // [128][16] swizzled
    float*  Kt  = (float*)(smem4 + TILE * 16);        // [64][KT_S] transposed

    const float* Qg = Q + ((size_t)z * L_SEQ + (size_t)ti * TILE) * D_DIM;
    const float* Kg = K + ((size_t)z * L_SEQ + (size_t)tj * TILE) * D_DIM;

    #pragma unroll
    for (int p = 0; p < 8; ++p) {
        int idx = tid + p * 256;
        int row = idx >> 4;
        int kq  = idx & 15;
        Qs4[row * 16 + (kq ^ ((row >> 3) & 7))] = ((const float4*)Qg)[idx];
    }
    #pragma unroll
    for (int p = 0; p < 8; ++p) {
        int idx = tid + p * 256;
        int c   = idx >> 4;
        int kq  = idx & 15;
        float4 v = ((const float4*)Kg)[idx];
        float* dst = &Kt[(4 * kq) * KT_S + c];
        dst[0 * KT_S] = v.x;
        dst[1 * KT_S] = v.y;
        dst[2 * KT_S] = v.z;
        dst[3 * KT_S] = v.w;
    }
    __syncthreads();

    const int ty  = tid >> 4;
    const int tx  = tid & 15;
    const int qsw = ty & 7;

    ull acc2[8][4];
    #pragma unroll
    for (int r = 0; r < 8; ++r)
        #pragma unroll
        for (int p = 0; p < 4; ++p) acc2[r][p] = 0ULL;

    #pragma unroll 4
    for (int kq = 0; kq < 16; ++kq) {
        ulonglong2 bA[4], bB[4];
        #pragma unroll
        for (int j = 0; j < 4; ++j) {
            const float* base = &Kt[(4 * kq + j) * KT_S + 4 * tx];
            bA[j] = *(const ulonglong2*)base;
            bB[j] = *(const ulonglong2*)(base + 64);
        }
        #pragma unroll
        for (int r = 0; r < 8; ++r) {
            float4 qv = Qs4[(8 * ty + r) * 16 + (kq ^ qsw)];
            #pragma unroll
            for (int j = 0; j < 4; ++j) {
                float q = (j == 0) ? qv.x : (j == 1) ? qv.y
                        : (j == 2) ? qv.z : qv.w;
                ull q2 = dup2(q);
                fma2(acc2[r][0], q2, bA[j].x);
                fma2(acc2[r][1], q2, bA[j].y);
                fma2(acc2[r][2], q2, bB[j].x);
                fma2(acc2[r][3], q2, bB[j].y);
            }
        }
    }

    if (ti == tj) {
        #pragma unroll
        for (int r = 0; r < 8; ++r) {
            float* orow = outTile + (size_t)(8 * ty + r) * L_SEQ;
            float2 p0 = unpack2(acc2[r][0]);
            float2 p1 = unpack2(acc2[r][1]);
            float2 p2 = unpack2(acc2[r][2]);
            float2 p3 = unpack2(acc2[r][3]);
            ((float4*)orow)[tx]        = make_float4(p0.x, p0.y, p1.x, p1.y);
            ((float4*)(orow + 64))[tx] = make_float4(p2.x, p2.y, p3.x, p3.y);
        }
        return;
    }

    // |ti-tj| == 1: partial band, mask per element
    const int gi0 = ti * TILE + 8 * ty;
    const int jA0 = tj * TILE + 4 * tx;
    const int jB0 = tj * TILE + 64 + 4 * tx;

    #pragma unroll
    for (int r = 0; r < 8; ++r) {
        const int gi = gi0 + r;
        float* orow = outTile + (size_t)(8 * ty + r) * L_SEQ;

        float2 p0 = unpack2(acc2[r][0]);
        float2 p1 = unpack2(acc2[r][1]);
        float2 p2 = unpack2(acc2[r][2]);
        float2 p3 = unpack2(acc2[r][3]);

        float4 vA, vB;
        {
            int d0 = gi - (jA0 + 0); if (d0 < 0) d0 = -d0;
            int d1 = gi - (jA0 + 1); if (d1 < 0) d1 = -d1;
            int d2 = gi - (jA0 + 2); if (d2 < 0) d2 = -d2;
            int d3 = gi - (jA0 + 3); if (d3 < 0) d3 = -d3;
            vA.x = (d0 <= R_BAND) ? p0.x : 0.f;
            vA.y = (d1 <= R_BAND) ? p0.y : 0.f;
            vA.z = (d2 <= R_BAND) ? p1.x : 0.f;
            vA.w = (d3 <= R_BAND) ? p1.y : 0.f;
        }
        {
            int d0 = gi - (jB0 + 0); if (d0 < 0) d0 = -d0;
            int d1 = gi - (jB0 + 1); if (d1 < 0) d1 = -d1;
            int d2 = gi - (jB0 + 2); if (d2 < 0) d2 = -d2;
            int d3 = gi - (jB0 + 3); if (d3 < 0) d3 = -d3;
            vB.x = (d0 <= R_BAND) ? p2.x : 0.f;
            vB.y = (d1 <= R_BAND) ? p2.y : 0.f;
            vB.z = (d2 <= R_BAND) ? p3.x : 0.f;
            vB.w = (d3 <= R_BAND) ? p3.y : 0.f;
        }

        ((float4*)orow)[tx]        = vA;
        ((float4*)(orow + 64))[tx] = vB;
    }
}

extern "C" void kernel_launch(void* const* d_in, const int* in_sizes, int n_in,
                              void* d_out, int out_size)
{
    const float* Q  = (const float*)d_in[0];
    const float* K  = (const float*)d_in[1];
    float*       out = (float*)d_out;

    const int smem_bytes = TILE * 16 * 16 + 64 * KT_S * 4;  // 66560

    cudaFuncSetAttribute(band_scores_kernel,
                         cudaFuncAttributeMaxDynamicSharedMemorySize,
                         smem_bytes);

    // Fork a side stream so fill and band kernels run CONCURRENTLY.
    // (Stream/event creation is not a captured op; objects are intentionally
    //  leaked — kernel_launch is invoked only for the correctness run and
    //  the single capture call. No device memory is allocated.)
    cudaStream_t s2;
    cudaStreamCreateWithFlags(&s2, cudaStreamNonBlocking);
    cudaEvent_t e_fork, e_join;
    cudaEventCreateWithFlags(&e_fork, cudaEventDisableTiming);
    cudaEventCreateWithFlags(&e_join, cudaEventDisableTiming);

    cudaEventRecord(e_fork, 0);             // fork from capture (legacy) stream
    cudaStreamWaitEvent(s2, e_fork, 0);

    zero_fill_kernel<<<N_FILL_CTAS, 128, 0, s2>>>(out);
    band_scores_kernel<<<N_BAND, 256, smem_bytes>>>(Q, K, out);

    cudaEventRecord(e_join, s2);            // join back into capture stream
    cudaStreamWaitEvent(0, e_join, 0);
}